// round 1
// baseline (speedup 1.0000x reference)
#include <cuda_runtime.h>
#include <math.h>

// ChamferLoss: B=8, N=M=4096, D=3
// inputs: d_in[0] = predicted_points [8,4096,3] f32, d_in[1] = target_points [8,4096,3] f32
// output: d_out[0] = scalar f32

#define BATCH   8
#define NPTS    4096
#define THREADS 256
#define CHUNK   2048   // targets staged per smem pass (32 KB of float4)

__device__ double g_sum;

__global__ void zero_acc_kernel() { g_sum = 0.0; }

__global__ void finalize_kernel(float* out) { out[0] = (float)g_sum; }

// One block handles THREADS source points of one batch, for one direction.
// grid = (NPTS/THREADS, BATCH, 2). z==0: src=pred,tgt=target; z==1: swapped.
__global__ __launch_bounds__(THREADS) void chamfer_dir_kernel(
    const float* __restrict__ pred,
    const float* __restrict__ targ)
{
    __shared__ float4 sm[CHUNK];
    __shared__ float warpsums[THREADS / 32];

    const int b   = blockIdx.y;
    const int dir = blockIdx.z;
    const float* __restrict__ sp = (dir == 0 ? pred : targ) + (size_t)b * NPTS * 3;
    const float* __restrict__ tp = (dir == 0 ? targ : pred) + (size_t)b * NPTS * 3;

    // This thread's source point
    const int i  = blockIdx.x * THREADS + threadIdx.x;
    const float px = sp[i * 3 + 0];
    const float py = sp[i * 3 + 1];
    const float pz = sp[i * 3 + 2];
    const float m0 = -2.0f * px;
    const float m1 = -2.0f * py;
    const float m2 = -2.0f * pz;

    float best = INFINITY;

    for (int c0 = 0; c0 < NPTS; c0 += CHUNK) {
        __syncthreads();  // protect sm[] from previous pass's readers
        // Stage CHUNK targets as (x, y, z, |t|^2)
        #pragma unroll
        for (int j = threadIdx.x; j < CHUNK; j += THREADS) {
            const float* t = tp + (size_t)(c0 + j) * 3;
            float x = t[0], y = t[1], z = t[2];
            sm[j] = make_float4(x, y, z, fmaf(x, x, fmaf(y, y, z * z)));
        }
        __syncthreads();

        // min over chunk of (|t|^2 - 2 p.t)  — 3 FFMA + 1 FMNMX per target
        #pragma unroll 8
        for (int j = 0; j < CHUNK; j++) {
            float4 t = sm[j];
            float v = fmaf(m0, t.x, fmaf(m1, t.y, fmaf(m2, t.z, t.w)));
            best = fminf(best, v);
        }
    }

    // true min squared distance = best + |p|^2 (clamped), then sqrt
    const float p2 = fmaf(px, px, fmaf(py, py, pz * pz));
    float d = sqrtf(fmaxf(best + p2, 0.0f));

    // block reduction of d
    float s = d;
    #pragma unroll
    for (int o = 16; o > 0; o >>= 1)
        s += __shfl_xor_sync(0xFFFFFFFFu, s, o);
    const int lane = threadIdx.x & 31;
    const int wid  = threadIdx.x >> 5;
    if (lane == 0) warpsums[wid] = s;
    __syncthreads();
    if (wid == 0) {
        float v = (lane < THREADS / 32) ? warpsums[lane] : 0.0f;
        #pragma unroll
        for (int o = 4; o > 0; o >>= 1)
            v += __shfl_xor_sync(0xFFFFFFFFu, v, o);
        if (lane == 0) {
            // both directions average over BATCH*NPTS points
            const double scale = 1.0 / ((double)BATCH * (double)NPTS);
            atomicAdd(&g_sum, (double)v * scale);
        }
    }
}

extern "C" void kernel_launch(void* const* d_in, const int* in_sizes, int n_in,
                              void* d_out, int out_size) {
    const float* pred = (const float*)d_in[0];
    const float* targ = (const float*)d_in[1];
    float* out = (float*)d_out;

    zero_acc_kernel<<<1, 1>>>();

    dim3 grid(NPTS / THREADS, BATCH, 2);
    chamfer_dir_kernel<<<grid, THREADS>>>(pred, targ);

    finalize_kernel<<<1, 1>>>(out);
}

// round 2
// speedup vs baseline: 1.0491x; 1.0491x over previous
#include <cuda_runtime.h>
#include <math.h>

// ChamferLoss: B=8, N=M=4096, D=3
// d_in[0] = predicted [8,4096,3] f32, d_in[1] = target [8,4096,3] f32, out = scalar f32

#define BATCH    8
#define NPTS     4096
#define THREADS  256
#define NGROUPS  (NPTS / 2)          // 2048 packed 2-target groups
#define NBLOCKS  256                 // 16 combos (b,dir) x 16 slices
#define SMEM_BYTES (NGROUPS * 2 * (int)sizeof(ulonglong2))   // 64 KB

__device__ double       g_sum  = 0.0;
__device__ unsigned int g_tick = 0;

static __device__ __forceinline__ unsigned long long pk2(float lo, float hi) {
    unsigned long long r;
    asm("mov.b64 %0, {%1, %2};" : "=l"(r) : "f"(lo), "f"(hi));
    return r;
}
static __device__ __forceinline__ unsigned long long fma2(unsigned long long a,
                                                          unsigned long long b,
                                                          unsigned long long c) {
    unsigned long long d;
    asm("fma.rn.f32x2 %0, %1, %2, %3;" : "=l"(d) : "l"(a), "l"(b), "l"(c));
    return d;
}
static __device__ __forceinline__ void unpk2(unsigned long long v, float& lo, float& hi) {
    asm("mov.b64 {%0, %1}, %2;" : "=f"(lo), "=f"(hi) : "l"(v));
}

__global__ __launch_bounds__(THREADS) void chamfer_kernel(
    const float* __restrict__ pred,
    const float* __restrict__ targ,
    float* __restrict__ out)
{
    extern __shared__ ulonglong2 sm[];     // [2*NGROUPS]: {x0x1,y0y1},{z0z1,w0w1} per group
    __shared__ float warpsums[THREADS / 32];

    const int combo = blockIdx.x >> 4;     // 0..15
    const int slice = blockIdx.x & 15;     // 0..15
    const int dir   = combo & 1;
    const int b     = combo >> 1;
    const float* __restrict__ sp = (dir == 0 ? pred : targ) + (size_t)b * NPTS * 3;
    const float* __restrict__ tp = (dir == 0 ? targ : pred) + (size_t)b * NPTS * 3;

    // Stage the full target cloud as packed pair-groups (x,y,z,|t|^2)
    for (int g = threadIdx.x; g < NGROUPS; g += THREADS) {
        const float* t = tp + 6 * g;
        float x0 = t[0], y0 = t[1], z0 = t[2];
        float x1 = t[3], y1 = t[4], z1 = t[5];
        float w0 = fmaf(x0, x0, fmaf(y0, y0, z0 * z0));
        float w1 = fmaf(x1, x1, fmaf(y1, y1, z1 * z1));
        sm[2 * g]     = make_ulonglong2(pk2(x0, x1), pk2(y0, y1));
        sm[2 * g + 1] = make_ulonglong2(pk2(z0, z1), pk2(w0, w1));
    }

    // This thread's source point
    const int i  = slice * THREADS + threadIdx.x;
    const float px = sp[3 * i + 0];
    const float py = sp[3 * i + 1];
    const float pz = sp[3 * i + 2];
    const unsigned long long mx = pk2(-2.0f * px, -2.0f * px);
    const unsigned long long my = pk2(-2.0f * py, -2.0f * py);
    const unsigned long long mz = pk2(-2.0f * pz, -2.0f * pz);

    __syncthreads();

    float best0 = INFINITY, best1 = INFINITY;
    #pragma unroll 8
    for (int g = 0; g < NGROUPS; g++) {
        ulonglong2 A = sm[2 * g];          // {x0x1, y0y1}
        ulonglong2 C = sm[2 * g + 1];      // {z0z1, w0w1}
        unsigned long long v = fma2(mz, C.x, C.y);
        v = fma2(my, A.y, v);
        v = fma2(mx, A.x, v);
        float vlo, vhi;
        unpk2(v, vlo, vhi);
        best0 = fminf(best0, vlo);
        best1 = fminf(best1, vhi);
    }

    const float p2 = fmaf(px, px, fmaf(py, py, pz * pz));
    float d = sqrtf(fmaxf(fminf(best0, best1) + p2, 0.0f));

    // Block reduction
    float s = d;
    #pragma unroll
    for (int o = 16; o > 0; o >>= 1)
        s += __shfl_xor_sync(0xFFFFFFFFu, s, o);
    const int lane = threadIdx.x & 31;
    const int wid  = threadIdx.x >> 5;
    if (lane == 0) warpsums[wid] = s;
    __syncthreads();
    if (wid == 0) {
        float v = (lane < THREADS / 32) ? warpsums[lane] : 0.0f;
        #pragma unroll
        for (int o = 4; o > 0; o >>= 1)
            v += __shfl_xor_sync(0xFFFFFFFFu, v, o);
        if (lane == 0) {
            const double scale = 1.0 / ((double)BATCH * (double)NPTS);
            atomicAdd(&g_sum, (double)v * scale);
            __threadfence();
            unsigned int done = atomicAdd(&g_tick, 1u);
            if (done == NBLOCKS - 1) {
                double total = atomicAdd(&g_sum, 0.0);   // atomic read
                out[0] = (float)total;
                g_sum  = 0.0;                             // reset for next graph replay
                g_tick = 0;
            }
        }
    }
}

extern "C" void kernel_launch(void* const* d_in, const int* in_sizes, int n_in,
                              void* d_out, int out_size) {
    const float* pred = (const float*)d_in[0];
    const float* targ = (const float*)d_in[1];
    float* out = (float*)d_out;

    static bool attr_set = false;
    if (!attr_set) {
        cudaFuncSetAttribute(chamfer_kernel,
                             cudaFuncAttributeMaxDynamicSharedMemorySize, SMEM_BYTES);
        attr_set = true;
    }

    chamfer_kernel<<<NBLOCKS, THREADS, SMEM_BYTES>>>(pred, targ, out);
}